// round 2
// baseline (speedup 1.0000x reference)
#include <cuda_runtime.h>
#include <cuda_fp16.h>
#include <cstdint>

#define DINLINE __device__ __forceinline__

// ---------------- problem constants ----------------
#define B_    32
#define F_    128
#define T_    4000
#define H_    256
#define TPAD  4096
#define NCH   40
#define LCH   100
#define EPS_  1e-6f

#define ASTRIDE 264   // halves per A-tile row (256 + 8 pad)
#define WSTRIDE 72    // halves per W-chunk row (64 + 8 pad)
#define GEMM_SMEM_BYTES ((64*ASTRIDE + 256*WSTRIDE) * 2)

// ---------------- device scratch (BSS) ----------------
__device__ float  g_Xt[(size_t)B_ * T_ * F_];      // [B][T][F]
__device__ __half g_W1t[256 * 256];                // [N=256][K=256]
__device__ __half g_W2t[512 * 256];                // [N=512][K=256]
__device__ __half g_H[(size_t)B_ * TPAD * H_];     // [B][TPAD][H]
__device__ float  g_s [(size_t)B_ * T_ * F_];      // [B][T][F]
__device__ float  g_al[(size_t)B_ * T_ * F_];
__device__ float  g_de[(size_t)B_ * T_ * F_];
__device__ float  g_r [(size_t)B_ * T_ * F_];
__device__ float  g_chA[NCH * B_ * F_];
__device__ float  g_chB[NCH * B_ * F_];
__device__ float  g_Mst[NCH * B_ * F_];

// ---------------- small helpers ----------------
DINLINE uint32_t smem_u32(const void* p) {
    uint32_t a;
    asm("{ .reg .u64 t; cvta.to.shared.u64 t, %1; cvt.u32.u64 %0, t; }" : "=r"(a) : "l"(p));
    return a;
}

DINLINE void ldsm_x4(uint32_t* r, uint32_t addr) {
    asm volatile("ldmatrix.sync.aligned.m8n8.x4.shared.b16 {%0,%1,%2,%3}, [%4];"
                 : "=r"(r[0]), "=r"(r[1]), "=r"(r[2]), "=r"(r[3]) : "r"(addr));
}
DINLINE void ldsm_x2(uint32_t* r, uint32_t addr) {
    asm volatile("ldmatrix.sync.aligned.m8n8.x2.shared.b16 {%0,%1}, [%2];"
                 : "=r"(r[0]), "=r"(r[1]) : "r"(addr));
}
DINLINE void mma16816(float* c, const uint32_t* a, const uint32_t* b) {
    asm volatile("mma.sync.aligned.m16n8k16.row.col.f32.f16.f16.f32 "
                 "{%0,%1,%2,%3}, {%4,%5,%6,%7}, {%8,%9}, {%0,%1,%2,%3};"
                 : "+f"(c[0]), "+f"(c[1]), "+f"(c[2]), "+f"(c[3])
                 : "r"(a[0]), "r"(a[1]), "r"(a[2]), "r"(a[3]), "r"(b[0]), "r"(b[1]));
}

DINLINE float sigmoidf_(float x) { return 1.0f / (1.0f + __expf(-x)); }
DINLINE float softplusf_(float x) { return (x > 20.0f) ? x : log1pf(__expf(x)); }

// ---------------- K0: weight transpose + fp16 convert ----------------
__global__ void k_wprep(const float* __restrict__ W1, const float* __restrict__ W2) {
    int idx = blockIdx.x * blockDim.x + threadIdx.x;
    if (idx < 256 * 256) {
        int k = idx >> 8, n = idx & 255;           // W1[k][n], k<2F=256, n<H=256
        g_W1t[n * 256 + k] = __float2half_rn(W1[idx]);
    } else {
        int i2 = idx - 256 * 256;
        if (i2 < 256 * 512) {
            int k = i2 >> 9, n = i2 & 511;         // W2[k][n], k<H=256, n<4F=512
            g_W2t[n * 256 + k] = __float2half_rn(W2[i2]);
        }
    }
}

// ---------------- K1: X [B][F][T] -> Xt [B][T][F] ----------------
__global__ void k_xt(const float* __restrict__ X) {
    __shared__ float tile[32][33];
    int b = blockIdx.z;
    int t0 = blockIdx.x * 32, f0 = blockIdx.y * 32;
    int tx = threadIdx.x, ty = threadIdx.y;
    #pragma unroll
    for (int j = 0; j < 4; j++) {
        int f = f0 + ty + j * 8;
        int t = t0 + tx;
        if (t < T_) tile[ty + j * 8][tx] = X[((size_t)b * F_ + f) * T_ + t];
    }
    __syncthreads();
    #pragma unroll
    for (int j = 0; j < 4; j++) {
        int t = t0 + ty + j * 8;
        int f = f0 + tx;
        if (t < T_) g_Xt[((size_t)b * T_ + t) * F_ + f] = tile[tx][ty + j * 8];
    }
}

// ---------------- GEMM1: H = relu([Xprev|Xcur] @ W1 + b1) ----------------
__global__ void __launch_bounds__(256) k_gemm1(const float* __restrict__ b1) {
    extern __shared__ __align__(16) __half dsm[];
    __half* As = dsm;                       // [64][ASTRIDE]
    __half* Ws = dsm + 64 * ASTRIDE;        // [256][WSTRIDE]

    int t0 = blockIdx.x * 64;
    int b  = blockIdx.y;
    int tid = threadIdx.x;
    int lane = tid & 31, warp = tid >> 5;
    int wn = warp * 32;

    // --- load A tile: row m -> [Xt[b][t-1][:128] | Xt[b][t][:128]] (t clamped) ---
    {
        int r = tid >> 2, q = tid & 3;
        int t = t0 + r;
        int tc = min(t, T_ - 1);
        int tp = min(max(t - 1, 0), T_ - 1);
        const float* rowp = g_Xt + ((size_t)b * T_ + tp) * F_;
        const float* rowc = g_Xt + ((size_t)b * T_ + tc) * F_;
        #pragma unroll
        for (int p = 0; p < 16; p++) {
            int col = q * 64 + p * 4;
            const float* src = (col < 128) ? (rowp + col) : (rowc + col - 128);
            float4 v = *(const float4*)src;
            __half2* dst = (__half2*)&As[r * ASTRIDE + col];
            dst[0] = __floats2half2_rn(v.x, v.y);
            dst[1] = __floats2half2_rn(v.z, v.w);
        }
    }

    float acc[4][4][4];
    #pragma unroll
    for (int i = 0; i < 4; i++)
        #pragma unroll
        for (int j = 0; j < 4; j++)
            #pragma unroll
            for (int v = 0; v < 4; v++) acc[i][j][v] = 0.0f;

    uint32_t As_b = smem_u32(As), Ws_b = smem_u32(Ws);

    for (int kc = 0; kc < 4; kc++) {
        __syncthreads();
        // load W chunk: Ws[n][0..63] = W1t[n][kc*64 ..]
        #pragma unroll
        for (int p = 0; p < 8; p++) {
            int idx = tid + p * 256;
            int n = idx >> 3, seg = idx & 7;
            int4 v = *(const int4*)(g_W1t + n * 256 + kc * 64 + seg * 8);
            *(int4*)&Ws[n * WSTRIDE + seg * 8] = v;
        }
        __syncthreads();
        #pragma unroll
        for (int kk = 0; kk < 4; kk++) {
            int kcol = kc * 64 + kk * 16;
            uint32_t a[4][4];
            #pragma unroll
            for (int i = 0; i < 4; i++) {
                int row = i * 16 + (lane & 15);
                int col = kcol + (lane >> 4) * 8;
                ldsm_x4(a[i], As_b + (row * ASTRIDE + col) * 2);
            }
            uint32_t bf[4][2];
            #pragma unroll
            for (int j = 0; j < 4; j++) {
                int l16 = lane & 15;
                int nrow = wn + j * 8 + (l16 & 7);
                int col = kk * 16 + (l16 >> 3) * 8;
                ldsm_x2(bf[j], Ws_b + (nrow * WSTRIDE + col) * 2);
            }
            #pragma unroll
            for (int i = 0; i < 4; i++)
                #pragma unroll
                for (int j = 0; j < 4; j++)
                    mma16816(acc[i][j], a[i], bf[j]);
        }
    }

    // --- epilogue: +b1, relu, store fp16 to g_H ---
    int l4 = lane >> 2, l2 = (lane & 3) * 2;
    #pragma unroll
    for (int j = 0; j < 4; j++) {
        int n0 = wn + j * 8 + l2;
        float bb0 = b1[n0], bb1 = b1[n0 + 1];
        #pragma unroll
        for (int i = 0; i < 4; i++) {
            int r0 = t0 + i * 16 + l4;
            int r1 = r0 + 8;
            float h00 = fmaxf(acc[i][j][0] + bb0, 0.0f);
            float h01 = fmaxf(acc[i][j][1] + bb1, 0.0f);
            float h10 = fmaxf(acc[i][j][2] + bb0, 0.0f);
            float h11 = fmaxf(acc[i][j][3] + bb1, 0.0f);
            *(__half2*)&g_H[((size_t)b * TPAD + r0) * H_ + n0] = __floats2half2_rn(h00, h01);
            *(__half2*)&g_H[((size_t)b * TPAD + r1) * H_ + n0] = __floats2half2_rn(h10, h11);
        }
    }
}

// ---------------- GEMM2: out = H @ W2 + b2, activation split ----------------
__global__ void __launch_bounds__(256) k_gemm2(const float* __restrict__ b2) {
    extern __shared__ __align__(16) __half dsm[];
    __half* As = dsm;
    __half* Ws = dsm + 64 * ASTRIDE;

    int t0 = blockIdx.x * 64;
    int b  = blockIdx.y;
    int nhalf = blockIdx.z;
    int tid = threadIdx.x;
    int lane = tid & 31, warp = tid >> 5;
    int wn = warp * 32;

    // --- load A tile from g_H ---
    #pragma unroll
    for (int p = 0; p < 8; p++) {
        int idx = tid + p * 256;
        int m = idx >> 5, seg = idx & 31;
        int4 v = *(const int4*)(g_H + ((size_t)b * TPAD + t0 + m) * H_ + seg * 8);
        *(int4*)&As[m * ASTRIDE + seg * 8] = v;
    }

    float acc[4][4][4];
    #pragma unroll
    for (int i = 0; i < 4; i++)
        #pragma unroll
        for (int j = 0; j < 4; j++)
            #pragma unroll
            for (int v = 0; v < 4; v++) acc[i][j][v] = 0.0f;

    uint32_t As_b = smem_u32(As), Ws_b = smem_u32(Ws);
    const __half* W2base = g_W2t + (size_t)nhalf * 256 * 256;

    for (int kc = 0; kc < 4; kc++) {
        __syncthreads();
        #pragma unroll
        for (int p = 0; p < 8; p++) {
            int idx = tid + p * 256;
            int n = idx >> 3, seg = idx & 7;
            int4 v = *(const int4*)(W2base + n * 256 + kc * 64 + seg * 8);
            *(int4*)&Ws[n * WSTRIDE + seg * 8] = v;
        }
        __syncthreads();
        #pragma unroll
        for (int kk = 0; kk < 4; kk++) {
            int kcol = kc * 64 + kk * 16;
            uint32_t a[4][4];
            #pragma unroll
            for (int i = 0; i < 4; i++) {
                int row = i * 16 + (lane & 15);
                int col = kcol + (lane >> 4) * 8;
                ldsm_x4(a[i], As_b + (row * ASTRIDE + col) * 2);
            }
            uint32_t bf[4][2];
            #pragma unroll
            for (int j = 0; j < 4; j++) {
                int l16 = lane & 15;
                int nrow = wn + j * 8 + (l16 & 7);
                int col = kk * 16 + (l16 >> 3) * 8;
                ldsm_x2(bf[j], Ws_b + (nrow * WSTRIDE + col) * 2);
            }
            #pragma unroll
            for (int i = 0; i < 4; i++)
                #pragma unroll
                for (int j = 0; j < 4; j++)
                    mma16816(acc[i][j], a[i], bf[j]);
        }
    }

    // --- epilogue: +b2, per-quarter activation, store fp32 [B][T][F] ---
    int l4 = lane >> 2, l2 = (lane & 3) * 2;
    #pragma unroll
    for (int j = 0; j < 4; j++) {
        int ng = nhalf * 256 + wn + j * 8 + l2;   // global output feature
        int q = ng >> 7;                          // 0:s 1:alpha 2:delta 3:r
        int f = ng & 127;
        float* outbuf = (q == 0) ? g_s : (q == 1) ? g_al : (q == 2) ? g_de : g_r;
        float bb0 = b2[ng], bb1 = b2[ng + 1];
        #pragma unroll
        for (int i = 0; i < 4; i++) {
            int r0 = t0 + i * 16 + l4;
            int r1 = r0 + 8;
            float v00 = acc[i][j][0] + bb0, v01 = acc[i][j][1] + bb1;
            float v10 = acc[i][j][2] + bb0, v11 = acc[i][j][3] + bb1;
            if (q == 2) {
                v00 = softplusf_(v00); v01 = softplusf_(v01);
                v10 = softplusf_(v10); v11 = softplusf_(v11);
            } else {
                v00 = sigmoidf_(v00); v01 = sigmoidf_(v01);
                v10 = sigmoidf_(v10); v11 = sigmoidf_(v11);
            }
            if (r0 < T_) *(float2*)&outbuf[((size_t)b * T_ + r0) * F_ + f] = make_float2(v00, v01);
            if (r1 < T_) *(float2*)&outbuf[((size_t)b * T_ + r1) * F_ + f] = make_float2(v10, v11);
        }
    }
}

// ---------------- K3a: per-chunk recurrence composition ----------------
__global__ void k_scan_a() {
    int ch = blockIdx.x, b = blockIdx.y, f = threadIdx.x;
    int t0 = ch * LCH;
    float Aa = 1.0f, Bb = 0.0f;
    const float* sp = g_s  + ((size_t)b * T_ + t0) * F_ + f;
    const float* xp = g_Xt + ((size_t)b * T_ + t0) * F_ + f;
    for (int tl = 0; tl < LCH; tl++) {
        float s = sp[tl * F_];
        float x = xp[tl * F_];
        float a = 1.0f - s;
        Bb = fmaf(a, Bb, s * x);
        Aa *= a;
    }
    g_chA[(ch * B_ + b) * F_ + f] = Aa;
    g_chB[(ch * B_ + b) * F_ + f] = Bb;
}

// ---------------- K3b: scan across chunks -> per-chunk start states ----------------
__global__ void k_scan_b() {
    int b = blockIdx.x, f = threadIdx.x;
    float M = 0.0f;
    for (int ch = 0; ch < NCH; ch++) {
        int idx = (ch * B_ + b) * F_ + f;
        g_Mst[idx] = M;
        M = fmaf(g_chA[idx], M, g_chB[idx]);
    }
}

// ---------------- K3c: replay recurrence + PCEN math + coalesced output ----------------
__global__ void k_scan_c(float* __restrict__ out) {
    __shared__ float tile[128][51];
    int ch = blockIdx.x, b = blockIdx.y, f = threadIdx.x;
    int t0 = ch * LCH;
    float M = g_Mst[(ch * B_ + b) * F_ + f];
    const size_t base = ((size_t)b * T_ + t0) * F_ + f;

    for (int half = 0; half < 2; half++) {
        int tb = half * 50;
        for (int tl = 0; tl < 50; tl++) {
            size_t o = base + (size_t)(tb + tl) * F_;
            float s  = g_s[o];
            float x  = g_Xt[o];
            float al = g_al[o];
            float de = g_de[o];
            float r  = g_r[o];
            M = fmaf(s, x - M, M);              // (1-s)*M + s*x
            float pM = __powf(M + EPS_, al);
            float u  = x / pM + de;
            float norm = __powf(u, r) - __powf(de, r);
            tile[f][tl] = norm;
        }
        __syncthreads();
        // flush: out[b][f][t] coalesced along t
        for (int p = 0; p < 50; p++) {
            int i = threadIdx.x + p * 128;
            int rr = i / 50, cc = i % 50;
            out[((size_t)b * F_ + rr) * T_ + t0 + tb + cc] = tile[rr][cc];
        }
        __syncthreads();
    }
}

// ---------------- launch ----------------
extern "C" void kernel_launch(void* const* d_in, const int* in_sizes, int n_in,
                              void* d_out, int out_size) {
    const float* X  = (const float*)d_in[0];
    const float* W1 = (const float*)d_in[1];
    const float* b1 = (const float*)d_in[2];
    const float* W2 = (const float*)d_in[3];
    const float* b2 = (const float*)d_in[4];
    float* out = (float*)d_out;

    cudaFuncSetAttribute(k_gemm1, cudaFuncAttributeMaxDynamicSharedMemorySize, GEMM_SMEM_BYTES);
    cudaFuncSetAttribute(k_gemm2, cudaFuncAttributeMaxDynamicSharedMemorySize, GEMM_SMEM_BYTES);

    int wtot = 256 * 256 + 256 * 512;
    k_wprep<<<(wtot + 255) / 256, 256>>>(W1, W2);
    k_xt<<<dim3((T_ + 31) / 32, F_ / 32, B_), dim3(32, 8)>>>(X);
    k_gemm1<<<dim3((T_ + 63) / 64, B_), 256, GEMM_SMEM_BYTES>>>(b1);
    k_gemm2<<<dim3((T_ + 63) / 64, B_, 2), 256, GEMM_SMEM_BYTES>>>(b2);
    k_scan_a<<<dim3(NCH, B_), 128>>>();
    k_scan_b<<<B_, 128>>>();
    k_scan_c<<<dim3(NCH, B_), 128>>>(out);
}

// round 4
// speedup vs baseline: 1.1025x; 1.1025x over previous
#include <cuda_runtime.h>
#include <cuda_fp16.h>
#include <cstdint>

#define DINLINE __device__ __forceinline__

// ---------------- problem constants ----------------
#define B_    32
#define F_    128
#define T_    4000
#define H_    256
#define NCH   40
#define LCH   100
#define EPS_  1e-6f

#define ASTRIDE 264     // halves per A/H-tile row (256 + 8 pad)
#define WSTRIDE 72      // halves per W-chunk row (64 + 8 pad)
#define ABYTES  (64 * ASTRIDE * 2)
#define WBYTES  (256 * WSTRIDE * 2)
#define OFF_W   ABYTES
#define SMEM_MLP (ABYTES + 2 * WBYTES)

// ---------------- device scratch (BSS) ----------------
__device__ float  g_Xt[(size_t)B_ * T_ * F_];      // [B][T][F]
__device__ __half g_W1t[256 * 256];                // [N=256][K=256]
__device__ __half g_W2t[512 * 256];                // [N=512][K=256]
__device__ float  g_s [(size_t)B_ * T_ * F_];      // [B][T][F]
__device__ float  g_al[(size_t)B_ * T_ * F_];
__device__ float  g_de[(size_t)B_ * T_ * F_];
__device__ float  g_r [(size_t)B_ * T_ * F_];
__device__ float  g_chA[NCH * B_ * F_];
__device__ float  g_chB[NCH * B_ * F_];
__device__ float  g_Mst[NCH * B_ * F_];

// ---------------- helpers ----------------
DINLINE uint32_t smem_u32(const void* p) {
    uint32_t a;
    asm("{ .reg .u64 t; cvta.to.shared.u64 t, %1; cvt.u32.u64 %0, t; }" : "=r"(a) : "l"(p));
    return a;
}
DINLINE void ldsm_x4(uint32_t* r, uint32_t addr) {
    asm volatile("ldmatrix.sync.aligned.m8n8.x4.shared.b16 {%0,%1,%2,%3}, [%4];"
                 : "=r"(r[0]), "=r"(r[1]), "=r"(r[2]), "=r"(r[3]) : "r"(addr));
}
DINLINE void ldsm_x2(uint32_t* r, uint32_t addr) {
    asm volatile("ldmatrix.sync.aligned.m8n8.x2.shared.b16 {%0,%1}, [%2];"
                 : "=r"(r[0]), "=r"(r[1]) : "r"(addr));
}
DINLINE void mma16816(float* c, const uint32_t* a, const uint32_t* b) {
    asm volatile("mma.sync.aligned.m16n8k16.row.col.f32.f16.f16.f32 "
                 "{%0,%1,%2,%3}, {%4,%5,%6,%7}, {%8,%9}, {%0,%1,%2,%3};"
                 : "+f"(c[0]), "+f"(c[1]), "+f"(c[2]), "+f"(c[3])
                 : "r"(a[0]), "r"(a[1]), "r"(a[2]), "r"(a[3]), "r"(b[0]), "r"(b[1]));
}
DINLINE void cp16(uint32_t dst, const void* src) {
    asm volatile("cp.async.cg.shared.global [%0], [%1], 16;" :: "r"(dst), "l"(src));
}
DINLINE void cp_commit() { asm volatile("cp.async.commit_group;" ::: "memory"); }
DINLINE void cp_wait0()  { asm volatile("cp.async.wait_group 0;" ::: "memory"); }

DINLINE float sigmoidf_(float x) { return 1.0f / (1.0f + __expf(-x)); }
DINLINE float softplusf_(float x) { return (x > 20.0f) ? x : log1pf(__expf(x)); }

// ---------------- K0: weight transpose + fp16 convert ----------------
__global__ void k_wprep(const float* __restrict__ W1, const float* __restrict__ W2) {
    int idx = blockIdx.x * blockDim.x + threadIdx.x;
    if (idx < 256 * 256) {
        int k = idx >> 8, n = idx & 255;           // W1[k][n]
        g_W1t[n * 256 + k] = __float2half_rn(W1[idx]);
    } else {
        int i2 = idx - 256 * 256;
        if (i2 < 256 * 512) {
            int k = i2 >> 9, n = i2 & 511;         // W2[k][n]
            g_W2t[n * 256 + k] = __float2half_rn(W2[i2]);
        }
    }
}

// ---------------- K1: X [B][F][T] -> Xt [B][T][F] ----------------
__global__ void k_xt(const float* __restrict__ X) {
    __shared__ float tile[32][33];
    int b = blockIdx.z;
    int t0 = blockIdx.x * 32, f0 = blockIdx.y * 32;
    int tx = threadIdx.x, ty = threadIdx.y;
    #pragma unroll
    for (int j = 0; j < 4; j++) {
        int f = f0 + ty + j * 8;
        int t = t0 + tx;
        tile[ty + j * 8][tx] = X[((size_t)b * F_ + f) * T_ + t];
    }
    __syncthreads();
    #pragma unroll
    for (int j = 0; j < 4; j++) {
        int t = t0 + ty + j * 8;
        int f = f0 + tx;
        g_Xt[((size_t)b * T_ + t) * F_ + f] = tile[tx][ty + j * 8];
    }
}

DINLINE const __half* chunk_base(int c) {
    if (c < 4) return g_W1t + c * 64;
    if (c < 8) return g_W2t + (c - 4) * 64;
    return g_W2t + 256 * 256 + (c - 8) * 64;
}

// ---------------- fused MLP: GEMM1 + relu + GEMM2 + activations ----------------
__global__ void __launch_bounds__(256, 2) k_mlp(const float* __restrict__ b1,
                                                const float* __restrict__ b2) {
    extern __shared__ __align__(16) char sm[];
    __half* As = (__half*)sm;
    uint32_t As_b = smem_u32(sm);
    uint32_t Ws_b = As_b + OFF_W;

    int t0 = blockIdx.x * 64;
    int b  = blockIdx.y;
    int tid = threadIdx.x;
    int lane = tid & 31, warp = tid >> 5;
    int wn = warp * 32;
    int l16 = lane & 15;

    // ---- A tile: row m -> [Xt[b][t-1][:128] | Xt[b][t][:128]] (t clamped) ----
    {
        int r = tid >> 2, q = tid & 3;
        int t = t0 + r;
        int tc = min(t, T_ - 1);
        int tp = min(max(t - 1, 0), T_ - 1);
        const float* rowp = g_Xt + ((size_t)b * T_ + tp) * F_;
        const float* rowc = g_Xt + ((size_t)b * T_ + tc) * F_;
        #pragma unroll
        for (int p = 0; p < 16; p++) {
            int col = q * 64 + p * 4;
            const float* src = (col < 128) ? (rowp + col) : (rowc + col - 128);
            float4 v = *(const float4*)src;
            __half2* dst = (__half2*)&As[r * ASTRIDE + col];
            dst[0] = __floats2half2_rn(v.x, v.y);
            dst[1] = __floats2half2_rn(v.z, v.w);
        }
    }

    float acc[4][4][4];
    #pragma unroll
    for (int i = 0; i < 4; i++)
        #pragma unroll
        for (int j = 0; j < 4; j++)
            #pragma unroll
            for (int v = 0; v < 4; v++) acc[i][j][v] = 0.0f;

    // fill weight chunk c into buffer sel
    auto fill = [&](int c, int sel) {
        const __half* base = chunk_base(c);
        uint32_t wb = Ws_b + sel * WBYTES;
        #pragma unroll
        for (int p = 0; p < 8; p++) {
            int idx = tid + p * 256;
            int n = idx >> 3, seg = idx & 7;
            cp16(wb + (n * WSTRIDE + seg * 8) * 2, base + n * 256 + seg * 8);
        }
        cp_commit();
    };

    auto mma_chunk = [&](int sel, int kc) {
        uint32_t wb = Ws_b + sel * WBYTES;
        #pragma unroll
        for (int kk = 0; kk < 4; kk++) {
            int kcol = kc * 64 + kk * 16;
            uint32_t a[4][4];
            #pragma unroll
            for (int i = 0; i < 4; i++) {
                int row = i * 16 + l16;
                int col = kcol + (lane >> 4) * 8;
                ldsm_x4(a[i], As_b + (row * ASTRIDE + col) * 2);
            }
            uint32_t bf[4][2];
            #pragma unroll
            for (int j = 0; j < 4; j++) {
                int nrow = wn + j * 8 + (l16 & 7);
                int col = kk * 16 + (l16 >> 3) * 8;
                ldsm_x2(bf[j], wb + (nrow * WSTRIDE + col) * 2);
            }
            #pragma unroll
            for (int i = 0; i < 4; i++)
                #pragma unroll
                for (int j = 0; j < 4; j++)
                    mma16816(acc[i][j], a[i], bf[j]);
        }
    };

    auto zero_acc = [&]() {
        #pragma unroll
        for (int i = 0; i < 4; i++)
            #pragma unroll
            for (int j = 0; j < 4; j++)
                #pragma unroll
                for (int v = 0; v < 4; v++) acc[i][j][v] = 0.0f;
    };

    int l4 = lane >> 2, l2 = (lane & 3) * 2;

    // epilogue 1: H = relu(acc + b1) -> As region (fp16)
    auto epi1 = [&]() {
        #pragma unroll
        for (int j = 0; j < 4; j++) {
            int n0 = wn + j * 8 + l2;
            float bb0 = b1[n0], bb1 = b1[n0 + 1];
            #pragma unroll
            for (int i = 0; i < 4; i++) {
                int r0 = i * 16 + l4;
                int r1 = r0 + 8;
                float h00 = fmaxf(acc[i][j][0] + bb0, 0.0f);
                float h01 = fmaxf(acc[i][j][1] + bb1, 0.0f);
                float h10 = fmaxf(acc[i][j][2] + bb0, 0.0f);
                float h11 = fmaxf(acc[i][j][3] + bb1, 0.0f);
                *(__half2*)&As[r0 * ASTRIDE + n0] = __floats2half2_rn(h00, h01);
                *(__half2*)&As[r1 * ASTRIDE + n0] = __floats2half2_rn(h10, h11);
            }
        }
    };

    // epilogue 2: activation split + store fp32 [B][T][F]
    auto epi2 = [&](int nbase) {
        #pragma unroll
        for (int j = 0; j < 4; j++) {
            int ng = nbase + wn + j * 8 + l2;
            int q = ng >> 7;                      // 0:s 1:alpha 2:delta 3:r
            int f = ng & 127;
            float* outbuf = (q == 0) ? g_s : (q == 1) ? g_al : (q == 2) ? g_de : g_r;
            float bb0 = b2[ng], bb1 = b2[ng + 1];
            #pragma unroll
            for (int i = 0; i < 4; i++) {
                int r0 = t0 + i * 16 + l4;
                int r1 = r0 + 8;
                float v00 = acc[i][j][0] + bb0, v01 = acc[i][j][1] + bb1;
                float v10 = acc[i][j][2] + bb0, v11 = acc[i][j][3] + bb1;
                if (q == 2) {
                    v00 = softplusf_(v00); v01 = softplusf_(v01);
                    v10 = softplusf_(v10); v11 = softplusf_(v11);
                } else {
                    v00 = sigmoidf_(v00); v01 = sigmoidf_(v01);
                    v10 = sigmoidf_(v10); v11 = sigmoidf_(v11);
                }
                if (r0 < T_) *(float2*)&outbuf[((size_t)b * T_ + r0) * F_ + f] = make_float2(v00, v01);
                if (r1 < T_) *(float2*)&outbuf[((size_t)b * T_ + r1) * F_ + f] = make_float2(v10, v11);
            }
        }
    };

    // ---- pipelined chunk stream: 0..3 W1, 4..7 W2 half0, 8..11 W2 half1 ----
    fill(0, 0);
    #pragma unroll 1
    for (int c = 0; c < 12; c++) {
        cp_wait0();
        __syncthreads();
        if (c == 4) {               // GEMM1 done (all warps past chunk-3 MMAs)
            epi1();
            zero_acc();
            __syncthreads();        // H visible before chunk-4 MMAs read it
        }
        if (c == 8) {               // phase 2a done (per-warp acc only)
            epi2(0);
            zero_acc();
        }
        if (c + 1 < 12) fill(c + 1, (c + 1) & 1);
        mma_chunk(c & 1, c & 3);
    }
    epi2(256);
}

// ---------------- K3a: per-chunk recurrence composition ----------------
__global__ void k_scan_a() {
    int ch = blockIdx.x, b = blockIdx.y, f = threadIdx.x;
    int t0 = ch * LCH;
    float Aa = 1.0f, Bb = 0.0f;
    const float* sp = g_s  + ((size_t)b * T_ + t0) * F_ + f;
    const float* xp = g_Xt + ((size_t)b * T_ + t0) * F_ + f;
    for (int tl = 0; tl < LCH; tl++) {
        float s = sp[tl * F_];
        float x = xp[tl * F_];
        float a = 1.0f - s;
        Bb = fmaf(a, Bb, s * x);
        Aa *= a;
    }
    g_chA[(ch * B_ + b) * F_ + f] = Aa;
    g_chB[(ch * B_ + b) * F_ + f] = Bb;
}

// ---------------- K3b: scan across chunks ----------------
__global__ void k_scan_b() {
    int b = blockIdx.x, f = threadIdx.x;
    float M = 0.0f;
    for (int ch = 0; ch < NCH; ch++) {
        int idx = (ch * B_ + b) * F_ + f;
        g_Mst[idx] = M;
        M = fmaf(g_chA[idx], M, g_chB[idx]);
    }
}

// ---------------- K3c: replay + PCEN + coalesced [B][F][T] output ----------------
__global__ void k_scan_c(float* __restrict__ out) {
    __shared__ float tile[128][51];
    int ch = blockIdx.x, b = blockIdx.y, f = threadIdx.x;
    int t0 = ch * LCH;
    float M = g_Mst[(ch * B_ + b) * F_ + f];
    const size_t base = ((size_t)b * T_ + t0) * F_ + f;

    for (int half = 0; half < 2; half++) {
        int tb = half * 50;
        for (int tl = 0; tl < 50; tl++) {
            size_t o = base + (size_t)(tb + tl) * F_;
            float s  = g_s[o];
            float x  = g_Xt[o];
            float al = g_al[o];
            float de = g_de[o];
            float r  = g_r[o];
            M = fmaf(s, x - M, M);
            float pM = __powf(M + EPS_, al);
            float u  = x / pM + de;
            float norm = __powf(u, r) - __powf(de, r);
            tile[f][tl] = norm;
        }
        __syncthreads();
        for (int p = 0; p < 50; p++) {
            int i = threadIdx.x + p * 128;
            int rr = i / 50, cc = i % 50;
            out[((size_t)b * F_ + rr) * T_ + t0 + tb + cc] = tile[rr][cc];
        }
        __syncthreads();
    }
}

// ---------------- launch ----------------
extern "C" void kernel_launch(void* const* d_in, const int* in_sizes, int n_in,
                              void* d_out, int out_size) {
    const float* X  = (const float*)d_in[0];
    const float* W1 = (const float*)d_in[1];
    const float* b1 = (const float*)d_in[2];
    const float* W2 = (const float*)d_in[3];
    const float* b2 = (const float*)d_in[4];
    float* out = (float*)d_out;

    cudaFuncSetAttribute(k_mlp, cudaFuncAttributeMaxDynamicSharedMemorySize, SMEM_MLP);

    int wtot = 256 * 256 + 256 * 512;
    k_wprep<<<(wtot + 255) / 256, 256>>>(W1, W2);
    k_xt<<<dim3(T_ / 32, F_ / 32, B_), dim3(32, 8)>>>(X);
    k_mlp<<<dim3((T_ + 63) / 64, B_), 256, SMEM_MLP>>>(b1, b2);
    k_scan_a<<<dim3(NCH, B_), 128>>>();
    k_scan_b<<<B_, 128>>>();
    k_scan_c<<<dim3(NCH, B_), 128>>>(out);
}